// round 1
// baseline (speedup 1.0000x reference)
#include <cuda_runtime.h>
#include <cuda_bf16.h>
#include <math.h>

// MovingNormalizationLayer: 1-D moving-window normalization along depth (last axis).
// x: [1,1,128,256,1024] fp32 -> out same shape.
// window = 100, pad = (50 left, 49 right) with zeros, denominator = 100 everywhere.
//
// Strategy: one CTA per 1024-element row. Build prefix sums of x and x^2 in
// shared memory via a two-level warp-shuffle scan, then each output is a
// difference of two (clamped) prefix entries. Memory-bound: 134MB in + 134MB out.

#define ROW_LEN 1024
#define WIN 100
#define HALF_L 50   // left reach (i-50 .. i+49)
#define THREADS 256 // 4 elements per thread

__device__ __forceinline__ float fixup(float r) {
    // jnp.nan_to_num(nan=0.0) defaults: posinf -> FLT_MAX, neginf -> -FLT_MAX
    if (isnan(r)) return 0.0f;
    if (isinf(r)) return (r > 0.0f) ? 3.4028234663852886e38f : -3.4028234663852886e38f;
    return r;
}

__global__ __launch_bounds__(THREADS, 8)
void moving_norm_kernel(const float* __restrict__ x, float* __restrict__ out) {
    __shared__ float sx[ROW_LEN];
    __shared__ float P [ROW_LEN + 1];
    __shared__ float P2[ROW_LEN + 1];
    __shared__ float wsum [THREADS / 32];
    __shared__ float wsum2[THREADS / 32];

    const int t    = threadIdx.x;
    const int lane = t & 31;
    const int wid  = t >> 5;
    const size_t row_off = (size_t)blockIdx.x * ROW_LEN;

    // ---- coalesced float4 load ----
    const float4 v = reinterpret_cast<const float4*>(x + row_off)[t];
    reinterpret_cast<float4*>(sx)[t] = v;

    // per-thread partial sums over its 4 contiguous elements
    const float s  = v.x + v.y + v.z + v.w;
    const float s2 = v.x * v.x + v.y * v.y + v.z * v.z + v.w * v.w;

    // ---- warp inclusive scan (pair) ----
    float inc = s, inc2 = s2;
    #pragma unroll
    for (int off = 1; off < 32; off <<= 1) {
        const float a = __shfl_up_sync(0xffffffffu, inc,  off);
        const float b = __shfl_up_sync(0xffffffffu, inc2, off);
        if (lane >= off) { inc += a; inc2 += b; }
    }
    if (lane == 31) { wsum[wid] = inc; wsum2[wid] = inc2; }
    __syncthreads();

    // offset from preceding warps (only 8 warps; serial add is cheap)
    float woff = 0.0f, woff2 = 0.0f;
    #pragma unroll
    for (int w = 0; w < THREADS / 32; ++w) {
        if (w < wid) { woff += wsum[w]; woff2 += wsum2[w]; }
    }
    const float excl  = woff  + inc  - s;   // exclusive prefix before this thread's 4 elems
    const float excl2 = woff2 + inc2 - s2;

    // ---- write prefix arrays P[0..1024] ----
    {
        const int b = 4 * t;
        float c  = excl,  c2 = excl2;
        c  += v.x;           c2 += v.x * v.x;           P[b + 1] = c;  P2[b + 1] = c2;
        c  += v.y;           c2 += v.y * v.y;           P[b + 2] = c;  P2[b + 2] = c2;
        c  += v.z;           c2 += v.z * v.z;           P[b + 3] = c;  P2[b + 3] = c2;
        c  += v.w;           c2 += v.w * v.w;           P[b + 4] = c;  P2[b + 4] = c2;
    }
    if (t == 0) { P[0] = 0.0f; P2[0] = 0.0f; }
    __syncthreads();

    // ---- compute 4 outputs per thread ----
    const float inv_n = 1.0f / (float)WIN;
    float4 o;
    #pragma unroll
    for (int k = 0; k < 4; ++k) {
        const int i  = 4 * t + k;
        const int lo = (i - HALF_L > 0)       ? (i - HALF_L) : 0;
        const int hi = (i + HALF_L < ROW_LEN) ? (i + HALF_L) : ROW_LEN;
        const float mean  = (P [hi] - P [lo]) * inv_n;
        const float mean2 = (P2[hi] - P2[lo]) * inv_n;
        const float stdv  = sqrtf(mean2 - mean * mean);
        const float r = (sx[i] - mean) / stdv;
        const float rr = fixup(r);
        if      (k == 0) o.x = rr;
        else if (k == 1) o.y = rr;
        else if (k == 2) o.z = rr;
        else             o.w = rr;
    }
    reinterpret_cast<float4*>(out + row_off)[t] = o;
}

extern "C" void kernel_launch(void* const* d_in, const int* in_sizes, int n_in,
                              void* d_out, int out_size) {
    const float* x = (const float*)d_in[0];
    float* out = (float*)d_out;
    const int total = in_sizes[0];          // 33,554,432
    const int rows  = total / ROW_LEN;      // 32,768
    moving_norm_kernel<<<rows, THREADS>>>(x, out);
}

// round 3
// speedup vs baseline: 1.7748x; 1.7748x over previous
#include <cuda_runtime.h>
#include <cuda_bf16.h>
#include <math.h>

// MovingNormalizationLayer: 1-D moving-window (w=100) normalization along the
// last axis of [1,1,128,256,1024] fp32. Zero-padded window, denominator = 100
// everywhere -> clamped prefix-sum differences.
//
// R1/R2: eliminate shared-memory bank conflicts.
//  - compute phase uses strided mapping i = t + 256k  -> lane-consecutive LDS
//  - exclusive-prefix layout lets each thread write its 4 P / P2 entries as a
//    single aligned STS.128 each (conflict-free)

#define ROW_LEN 1024
#define WIN 100
#define HALF_L 50
#define THREADS 256

__device__ __forceinline__ float fixup(float r) {
    // jnp.nan_to_num defaults: nan->0, +inf->FLT_MAX, -inf->-FLT_MAX
    if (isnan(r)) return 0.0f;
    if (isinf(r)) return (r > 0.0f) ? 3.4028234663852886e38f : -3.4028234663852886e38f;
    return r;
}

__global__ __launch_bounds__(THREADS, 8)
void moving_norm_kernel(const float* __restrict__ x, float* __restrict__ out) {
    __shared__ float sx[ROW_LEN];
    __shared__ float P [ROW_LEN + 4];   // exclusive prefix: P[i] = sum x[0..i)
    __shared__ float P2[ROW_LEN + 4];
    __shared__ float wsum [THREADS / 32];
    __shared__ float wsum2[THREADS / 32];

    const int t    = threadIdx.x;
    const int lane = t & 31;
    const int wid  = t >> 5;
    const size_t row_off = (size_t)blockIdx.x * ROW_LEN;

    // ---- coalesced float4 load of this thread's 4 contiguous elements ----
    const float4 v = reinterpret_cast<const float4*>(x + row_off)[t];
    reinterpret_cast<float4*>(sx)[t] = v;          // conflict-free STS.128

    const float s  = v.x + v.y + v.z + v.w;
    const float s2 = v.x * v.x + v.y * v.y + v.z * v.z + v.w * v.w;

    // ---- warp inclusive scan (pair) ----
    float inc = s, inc2 = s2;
    #pragma unroll
    for (int off = 1; off < 32; off <<= 1) {
        const float a = __shfl_up_sync(0xffffffffu, inc,  off);
        const float b = __shfl_up_sync(0xffffffffu, inc2, off);
        if (lane >= off) { inc += a; inc2 += b; }
    }
    if (lane == 31) { wsum[wid] = inc; wsum2[wid] = inc2; }
    __syncthreads();

    float woff = 0.0f, woff2 = 0.0f;
    #pragma unroll
    for (int w = 0; w < THREADS / 32; ++w) {
        if (w < wid) { woff += wsum[w]; woff2 += wsum2[w]; }
    }
    const float excl  = woff  + inc  - s;    // exclusive prefix before 4t
    const float excl2 = woff2 + inc2 - s2;

    // ---- write exclusive prefixes for positions 4t..4t+3 as one STS.128 each ----
    {
        float4 p, q;
        p.x = excl;
        p.y = p.x + v.x;
        p.z = p.y + v.y;
        p.w = p.z + v.z;
        q.x = excl2;
        q.y = q.x + v.x * v.x;
        q.z = q.y + v.y * v.y;
        q.w = q.z + v.z * v.z;
        reinterpret_cast<float4*>(P )[t] = p;   // aligned, conflict-free
        reinterpret_cast<float4*>(P2)[t] = q;
        if (t == THREADS - 1) {                 // total sums -> P[1024]
            P [ROW_LEN] = excl  + s;
            P2[ROW_LEN] = excl2 + s2;
        }
    }
    __syncthreads();

    // ---- compute, strided mapping: lanes read consecutive shared addresses ----
    const float inv_n = 1.0f / (float)WIN;
    #pragma unroll
    for (int k = 0; k < 4; ++k) {
        const int i  = t + k * THREADS;
        const int lo = (i - HALF_L > 0)       ? (i - HALF_L) : 0;
        const int hi = (i + HALF_L < ROW_LEN) ? (i + HALF_L) : ROW_LEN;
        const float mean  = (P [hi] - P [lo]) * inv_n;
        const float mean2 = (P2[hi] - P2[lo]) * inv_n;
        const float stdv  = sqrtf(mean2 - mean * mean);
        const float r  = (sx[i] - mean) / stdv;
        out[row_off + i] = fixup(r);             // coalesced STG.32
    }
}

extern "C" void kernel_launch(void* const* d_in, const int* in_sizes, int n_in,
                              void* d_out, int out_size) {
    const float* x = (const float*)d_in[0];
    float* out = (float*)d_out;
    const int total = in_sizes[0];          // 33,554,432
    const int rows  = total / ROW_LEN;      // 32,768
    moving_norm_kernel<<<rows, THREADS>>>(x, out);
}

// round 4
// speedup vs baseline: 1.7960x; 1.0120x over previous
#include <cuda_runtime.h>
#include <cuda_bf16.h>
#include <math.h>

// MovingNormalizationLayer: 1-D moving-window (w=100) normalization along the
// last axis of [1,1,128,256,1024] fp32. Zero-padded window, denominator = 100
// everywhere -> clamped prefix-sum differences.
//
// R1/R2: eliminate shared-memory bank conflicts.
//  - compute phase uses strided mapping i = t + 256k  -> lane-consecutive LDS
//  - exclusive-prefix layout lets each thread write its 4 P / P2 entries as a
//    single aligned STS.128 each (conflict-free)

#define ROW_LEN 1024
#define WIN 100
#define HALF_L 50
#define THREADS 256

__device__ __forceinline__ float fixup(float r) {
    // jnp.nan_to_num defaults: nan->0, +inf->FLT_MAX, -inf->-FLT_MAX
    if (isnan(r)) return 0.0f;
    if (isinf(r)) return (r > 0.0f) ? 3.4028234663852886e38f : -3.4028234663852886e38f;
    return r;
}

__global__ __launch_bounds__(THREADS, 8)
void moving_norm_kernel(const float* __restrict__ x, float* __restrict__ out) {
    __shared__ float sx[ROW_LEN];
    __shared__ float P [ROW_LEN + 4];   // exclusive prefix: P[i] = sum x[0..i)
    __shared__ float P2[ROW_LEN + 4];
    __shared__ float wsum [THREADS / 32];
    __shared__ float wsum2[THREADS / 32];

    const int t    = threadIdx.x;
    const int lane = t & 31;
    const int wid  = t >> 5;
    const size_t row_off = (size_t)blockIdx.x * ROW_LEN;

    // ---- coalesced float4 load of this thread's 4 contiguous elements ----
    const float4 v = reinterpret_cast<const float4*>(x + row_off)[t];
    reinterpret_cast<float4*>(sx)[t] = v;          // conflict-free STS.128

    const float s  = v.x + v.y + v.z + v.w;
    const float s2 = v.x * v.x + v.y * v.y + v.z * v.z + v.w * v.w;

    // ---- warp inclusive scan (pair) ----
    float inc = s, inc2 = s2;
    #pragma unroll
    for (int off = 1; off < 32; off <<= 1) {
        const float a = __shfl_up_sync(0xffffffffu, inc,  off);
        const float b = __shfl_up_sync(0xffffffffu, inc2, off);
        if (lane >= off) { inc += a; inc2 += b; }
    }
    if (lane == 31) { wsum[wid] = inc; wsum2[wid] = inc2; }
    __syncthreads();

    float woff = 0.0f, woff2 = 0.0f;
    #pragma unroll
    for (int w = 0; w < THREADS / 32; ++w) {
        if (w < wid) { woff += wsum[w]; woff2 += wsum2[w]; }
    }
    const float excl  = woff  + inc  - s;    // exclusive prefix before 4t
    const float excl2 = woff2 + inc2 - s2;

    // ---- write exclusive prefixes for positions 4t..4t+3 as one STS.128 each ----
    {
        float4 p, q;
        p.x = excl;
        p.y = p.x + v.x;
        p.z = p.y + v.y;
        p.w = p.z + v.z;
        q.x = excl2;
        q.y = q.x + v.x * v.x;
        q.z = q.y + v.y * v.y;
        q.w = q.z + v.z * v.z;
        reinterpret_cast<float4*>(P )[t] = p;   // aligned, conflict-free
        reinterpret_cast<float4*>(P2)[t] = q;
        if (t == THREADS - 1) {                 // total sums -> P[1024]
            P [ROW_LEN] = excl  + s;
            P2[ROW_LEN] = excl2 + s2;
        }
    }
    __syncthreads();

    // ---- compute, strided mapping: lanes read consecutive shared addresses ----
    const float inv_n = 1.0f / (float)WIN;
    #pragma unroll
    for (int k = 0; k < 4; ++k) {
        const int i  = t + k * THREADS;
        const int lo = (i - HALF_L > 0)       ? (i - HALF_L) : 0;
        const int hi = (i + HALF_L < ROW_LEN) ? (i + HALF_L) : ROW_LEN;
        const float mean  = (P [hi] - P [lo]) * inv_n;
        const float mean2 = (P2[hi] - P2[lo]) * inv_n;
        const float stdv  = sqrtf(mean2 - mean * mean);
        const float r  = (sx[i] - mean) / stdv;
        out[row_off + i] = fixup(r);             // coalesced STG.32
    }
}

extern "C" void kernel_launch(void* const* d_in, const int* in_sizes, int n_in,
                              void* d_out, int out_size) {
    const float* x = (const float*)d_in[0];
    float* out = (float*)d_out;
    const int total = in_sizes[0];          // 33,554,432
    const int rows  = total / ROW_LEN;      // 32,768
    moving_norm_kernel<<<rows, THREADS>>>(x, out);
}